// round 7
// baseline (speedup 1.0000x reference)
#include <cuda_runtime.h>

#define BB 256
#define DD 5120
#define NN 16
#define RR 160
#define JJ 192          // RR + 32 (B/C projections)
#define KSPLIT 80
#define KCH (DD / KSPLIT)   // 64
#define BK 16

// Scratch (device globals — no allocations allowed)
__device__ float g_P[KSPLIT * BB * JJ];   // split-K partials (15.7 MB)
__device__ float g_T[BB * JJ];            // reduced projections
__device__ float g_DT[BB * DD];           // dt (5.2 MB)

__device__ __forceinline__ float ex2f(float v) {
    float r;
    asm("ex2.approx.ftz.f32 %0, %1;" : "=f"(r) : "f"(v));
    return r;
}

typedef unsigned long long ull;

__device__ __forceinline__ ull fma2(ull a, ull b, ull c) {
    ull d;
    asm("fma.rn.f32x2 %0, %1, %2, %3;" : "=l"(d) : "l"(a), "l"(b), "l"(c));
    return d;
}
__device__ __forceinline__ float2 unpk(ull v) {
    float2 r;
    asm("mov.b64 {%0, %1}, %2;" : "=f"(r.x), "=f"(r.y) : "l"(v));
    return r;
}

// ---------------------------------------------------------------------------
// Kernel 1: split-K GEMM. P[ks] = x[:, k-chunk] @ [W_x_dt | W_BC]
// Tile 128(M) x 64(N), BK=16, double-buffered, 256 threads.
// Micro-tile 8M x 4N. As stored [k][m] DUPLICATED (float2 (v,v)): one
// LDS.128 yields TWO FFMA2-ready a-operands -> 1.25 smem B/FMA, zero MOVs.
// Grid (2, 3, 80) = 480 blocks (~3.2/SM).
// ---------------------------------------------------------------------------
__global__ __launch_bounds__(256) void mamba_proj_kernel(
    const float* __restrict__ x, const float* __restrict__ Wx,
    const float* __restrict__ Wbc)
{
    __shared__ float2 As2[2][BK][130];  // [buf][k][m] duplicated, padded
    __shared__ float  Bs[2][BK][64];    // [buf][k][n]
    const int m0 = blockIdx.x * 128;
    const int n0 = blockIdx.y * 64;
    const int k0 = blockIdx.z * KCH;
    const int tid = threadIdx.x;
    const int tx = tid & 15, ty = tid >> 4;   // micro coords: n=tx*4, m=ty*8

    const int am = tid >> 2, akq = (tid & 3) << 2;   // A loader
    const int bk_ = tid >> 4, bn = (tid & 15) << 2;  // B loader

    // Branch-free W source (column j fixed per thread)
    const int j = n0 + bn;
    const float* bbase;
    size_t bstride;
    if (j < RR) { bbase = Wx + j;         bstride = RR; }
    else        { bbase = Wbc + (j - RR); bstride = 32; }

    const float* a0src = &x[(size_t)(m0 + am) * DD + k0 + akq];
    const float* a1src = a0src + (size_t)64 * DD;

    ull acc2[8][2] = {};

    // prologue: chunk 0
    float4 av0 = *(const float4*)a0src;
    float4 av1 = *(const float4*)a1src;
    float4 bv  = *(const float4*)&bbase[(size_t)(k0 + bk_) * bstride];
#pragma unroll
    for (int q = 0; q < 4; q++) {
        float a0 = ((const float*)&av0)[q], a1 = ((const float*)&av1)[q];
        As2[0][akq + q][am]      = make_float2(a0, a0);
        As2[0][akq + q][am + 64] = make_float2(a1, a1);
    }
    *(float4*)&Bs[0][bk_][bn] = bv;
    __syncthreads();

#pragma unroll
    for (int c = 0; c < KCH / BK; c++) {
        const int cur = c & 1;
        if (c + 1 < KCH / BK) {
            av0 = *(const float4*)(a0src + (c + 1) * BK);
            av1 = *(const float4*)(a1src + (c + 1) * BK);
            bv  = *(const float4*)&bbase[(size_t)(k0 + (c + 1) * BK + bk_) * bstride];
        }
#pragma unroll
        for (int kk = 0; kk < BK; kk++) {
            ulonglong2 bq = *(const ulonglong2*)&Bs[cur][kk][tx * 4];
            ulonglong2 aq0 = *(const ulonglong2*)&As2[cur][kk][ty * 8 + 0];
            ulonglong2 aq1 = *(const ulonglong2*)&As2[cur][kk][ty * 8 + 2];
            ulonglong2 aq2 = *(const ulonglong2*)&As2[cur][kk][ty * 8 + 4];
            ulonglong2 aq3 = *(const ulonglong2*)&As2[cur][kk][ty * 8 + 6];
            acc2[0][0] = fma2(aq0.x, bq.x, acc2[0][0]);
            acc2[0][1] = fma2(aq0.x, bq.y, acc2[0][1]);
            acc2[1][0] = fma2(aq0.y, bq.x, acc2[1][0]);
            acc2[1][1] = fma2(aq0.y, bq.y, acc2[1][1]);
            acc2[2][0] = fma2(aq1.x, bq.x, acc2[2][0]);
            acc2[2][1] = fma2(aq1.x, bq.y, acc2[2][1]);
            acc2[3][0] = fma2(aq1.y, bq.x, acc2[3][0]);
            acc2[3][1] = fma2(aq1.y, bq.y, acc2[3][1]);
            acc2[4][0] = fma2(aq2.x, bq.x, acc2[4][0]);
            acc2[4][1] = fma2(aq2.x, bq.y, acc2[4][1]);
            acc2[5][0] = fma2(aq2.y, bq.x, acc2[5][0]);
            acc2[5][1] = fma2(aq2.y, bq.y, acc2[5][1]);
            acc2[6][0] = fma2(aq3.x, bq.x, acc2[6][0]);
            acc2[6][1] = fma2(aq3.x, bq.y, acc2[6][1]);
            acc2[7][0] = fma2(aq3.y, bq.x, acc2[7][0]);
            acc2[7][1] = fma2(aq3.y, bq.y, acc2[7][1]);
        }
        if (c + 1 < KCH / BK) {
            const int nxt = cur ^ 1;
            __syncthreads();
#pragma unroll
            for (int q = 0; q < 4; q++) {
                float a0 = ((const float*)&av0)[q], a1 = ((const float*)&av1)[q];
                As2[nxt][akq + q][am]      = make_float2(a0, a0);
                As2[nxt][akq + q][am + 64] = make_float2(a1, a1);
            }
            *(float4*)&Bs[nxt][bk_][bn] = bv;
            __syncthreads();
        }
    }

    float* dst = &g_P[(size_t)blockIdx.z * (BB * JJ)];
#pragma unroll
    for (int i = 0; i < 8; i++) {
        float2 p0 = unpk(acc2[i][0]);
        float2 p1 = unpk(acc2[i][1]);
        *(float4*)&dst[(size_t)(m0 + ty * 8 + i) * JJ + n0 + tx * 4] =
            make_float4(p0.x, p0.y, p1.x, p1.y);
    }
}

// ---------------------------------------------------------------------------
// Kernel 1r: reduce split-K partials. One thread per float, grid 192.
// ---------------------------------------------------------------------------
__global__ __launch_bounds__(256) void mamba_reduce_kernel()
{
    const int idx = blockIdx.x * 256 + threadIdx.x;
    float s = 0.f;
#pragma unroll 16
    for (int ks = 0; ks < KSPLIT; ks++) s += g_P[ks * (BB * JJ) + idx];
    g_T[idx] = s;
}

// ---------------------------------------------------------------------------
// Kernel 2a: dt GEMM.  z = t @ W_dt + b_dt ; dt = softplus(z) -> g_DT
// Tile 32(b) x 128(d), 256 threads, thread owns 4b x 4 consecutive d.
// Ts stored PRE-DUPLICATED: broadcast LDS.64 is directly the FFMA2 operand.
// Grid (40, 8).
// ---------------------------------------------------------------------------
__global__ __launch_bounds__(256) void mamba_dt_kernel(
    const float* __restrict__ Wdt, const float* __restrict__ bdt)
{
    const int d0 = blockIdx.x * 128;
    const int b0 = blockIdx.y * 32;
    const int tid = threadIdx.x;
    const int tdx = tid & 31;     // d lane (4 consecutive d)
    const int tby = tid >> 5;     // warp id = b group (4 b per warp)

    __shared__ float2 Ts2[32][160];  // t tile, duplicated (41 KB)
    __shared__ float  Ws[16][128];   // W_dt chunk
    __shared__ float  bds[128];

    for (int v = tid; v < 1280; v += 256) {
        int b = v / 40, r4 = (v - b * 40) * 4;
        float4 t4 = *(const float4*)&g_T[(b0 + b) * JJ + r4];
        Ts2[b][r4 + 0] = make_float2(t4.x, t4.x);
        Ts2[b][r4 + 1] = make_float2(t4.y, t4.y);
        Ts2[b][r4 + 2] = make_float2(t4.z, t4.z);
        Ts2[b][r4 + 3] = make_float2(t4.w, t4.w);
    }
    if (tid < 128) bds[tid] = bdt[d0 + tid];

    ull acc2[4][2] = {};
    const int wr = tid >> 4;          // 0..15
    const int wc = (tid & 15) << 3;   // 0..120
    for (int rc = 0; rc < RR; rc += 16) {
        const float* wsrc = &Wdt[(size_t)(rc + wr) * DD + d0 + wc];
        float4 w0 = *(const float4*)wsrc;
        float4 w1 = *(const float4*)(wsrc + 4);
        __syncthreads();
        *(float4*)&Ws[wr][wc] = w0;
        *(float4*)&Ws[wr][wc + 4] = w1;
        __syncthreads();
#pragma unroll
        for (int rr = 0; rr < 16; rr++) {
            ulonglong2 wq = *(const ulonglong2*)&Ws[rr][tdx * 4];
            ull a0 = *(const ull*)&Ts2[tby * 4 + 0][rc + rr];  // bcast LDS.64
            ull a1 = *(const ull*)&Ts2[tby * 4 + 1][rc + rr];
            ull a2 = *(const ull*)&Ts2[tby * 4 + 2][rc + rr];
            ull a3 = *(const ull*)&Ts2[tby * 4 + 3][rc + rr];
            acc2[0][0] = fma2(a0, wq.x, acc2[0][0]);
            acc2[0][1] = fma2(a0, wq.y, acc2[0][1]);
            acc2[1][0] = fma2(a1, wq.x, acc2[1][0]);
            acc2[1][1] = fma2(a1, wq.y, acc2[1][1]);
            acc2[2][0] = fma2(a2, wq.x, acc2[2][0]);
            acc2[2][1] = fma2(a2, wq.y, acc2[2][1]);
            acc2[3][0] = fma2(a3, wq.x, acc2[3][0]);
            acc2[3][1] = fma2(a3, wq.y, acc2[3][1]);
        }
    }

    float4 bdv = *(const float4*)&bds[tdx * 4];
#pragma unroll
    for (int bi = 0; bi < 4; bi++) {
        const int bl = tby * 4 + bi;
        float2 p0 = unpk(acc2[bi][0]);
        float2 p1 = unpk(acc2[bi][1]);
        float z0 = p0.x + bdv.x, z1 = p0.y + bdv.y;
        float z2 = p1.x + bdv.z, z3 = p1.y + bdv.w;
        float4 dtv;
        dtv.x = fmaxf(z0, 0.f) + log1pf(__expf(-fabsf(z0)));
        dtv.y = fmaxf(z1, 0.f) + log1pf(__expf(-fabsf(z1)));
        dtv.z = fmaxf(z2, 0.f) + log1pf(__expf(-fabsf(z2)));
        dtv.w = fmaxf(z3, 0.f) + log1pf(__expf(-fabsf(z3)));
        *(float4*)&g_DT[(size_t)(b0 + bl) * DD + d0 + tdx * 4] = dtv;
    }
}

// ---------------------------------------------------------------------------
// Kernel 2b: h0 stream, dual-stream depth-2 prefetch (4 LDGs in flight/warp).
//   y[b,d] = sum_n ex2(A2[d,n]*dt)*h0[b,d,n]*C[b,n] + dt*x*SBC[b] + x
// Block = (128 d, 16 b), 256 threads, 8 warps; warp w owns b in {2w, 2w+1},
// streams both b's contiguous 8 KB h0 regions simultaneously.
// Grid (40, 16) = 640 blocks.
// ---------------------------------------------------------------------------
__global__ __launch_bounds__(256) void mamba_scan_kernel(
    const float* __restrict__ x, const float* __restrict__ h0,
    const float* __restrict__ Alog, float* __restrict__ out)
{
    const int d0 = blockIdx.x * 128;
    const int b0 = blockIdx.y * 16;
    const int tid = threadIdx.x;
    const int lane = tid & 31;
    const int w = tid >> 5;

    __shared__ float A2s[128][16];   // -exp(A_log)*log2(e)
    __shared__ float dt_s[16][128];
    __shared__ float y_s[16][128];
    __shared__ float Cs[16][16];
    __shared__ float SBCs[16];

    // A2s (vectorized exp)
#pragma unroll
    for (int v = tid; v < 512; v += 256) {
        int di = v >> 2, n4 = (v & 3) << 2;
        float4 al = *(const float4*)&Alog[(size_t)(d0 + di) * NN + n4];
        float4 o;
        o.x = -__expf(al.x) * 1.44269504f;
        o.y = -__expf(al.y) * 1.44269504f;
        o.z = -__expf(al.z) * 1.44269504f;
        o.w = -__expf(al.w) * 1.44269504f;
        *(float4*)&A2s[di][n4] = o;
    }
    // dt tile
#pragma unroll
    for (int v = tid; v < 512; v += 256) {
        int b = v >> 5, dq = (v & 31) << 2;
        *(float4*)&dt_s[b][dq] =
            *(const float4*)&g_DT[(size_t)(b0 + b) * DD + d0 + dq];
    }
    // C, SBC
    {
        int b = tid >> 4, n = tid & 15;
        Cs[b][n] = g_T[(b0 + b) * JJ + RR + NN + n];
    }
    if (tid < 16) {
        float s = 0.f;
#pragma unroll
        for (int n = 0; n < NN; n++)
            s += g_T[(b0 + tid) * JJ + RR + n] * g_T[(b0 + tid) * JJ + RR + NN + n];
        SBCs[tid] = s;
    }
    __syncthreads();

    // Dual-stream coalesced h0 sweep. Lane l -> (d = dg*8 + l/4, n=(l&3)*4..+3).
    {
        const int l4 = lane >> 2;
        const int n4 = (lane & 3) << 2;
        const int bA = w * 2, bB = w * 2 + 1;

        const float* hpA = &h0[((size_t)(b0 + bA) * DD + d0 + l4) * NN + n4];
        const float* hpB = hpA + (size_t)DD * NN;

        const float4 cA = *(const float4*)&Cs[bA][n4];   // hoisted
        const float4 cB = *(const float4*)&Cs[bB][n4];

        float4 hA0 = __ldcs((const float4*)hpA);
        float4 hB0 = __ldcs((const float4*)hpB);
        float4 hA1 = __ldcs((const float4*)(hpA + 128));
        float4 hB1 = __ldcs((const float4*)(hpB + 128));

#pragma unroll
        for (int dg = 0; dg < 16; dg++) {
            const int dloc = dg * 8 + l4;
            const float4 a2 = *(const float4*)&A2s[dloc][n4];
            const float dtA = dt_s[bA][dloc];
            const float dtB = dt_s[bB][dloc];

            float pA = ex2f(a2.x * dtA) * hA0.x * cA.x;
            pA = fmaf(ex2f(a2.y * dtA) * hA0.y, cA.y, pA);
            pA = fmaf(ex2f(a2.z * dtA) * hA0.z, cA.z, pA);
            pA = fmaf(ex2f(a2.w * dtA) * hA0.w, cA.w, pA);

            float pB = ex2f(a2.x * dtB) * hB0.x * cB.x;
            pB = fmaf(ex2f(a2.y * dtB) * hB0.y, cB.y, pB);
            pB = fmaf(ex2f(a2.z * dtB) * hB0.z, cB.z, pB);
            pB = fmaf(ex2f(a2.w * dtB) * hB0.w, cB.w, pB);

            // rotate pipeline, keep 2 loads in flight per stream
            hA0 = hA1; hB0 = hB1;
            if (dg < 14) {
                hA1 = __ldcs((const float4*)(hpA + (size_t)(dg + 2) * 128));
                hB1 = __ldcs((const float4*)(hpB + (size_t)(dg + 2) * 128));
            }

            pA += __shfl_xor_sync(0xffffffffu, pA, 1);
            pA += __shfl_xor_sync(0xffffffffu, pA, 2);
            pB += __shfl_xor_sync(0xffffffffu, pB, 1);
            pB += __shfl_xor_sync(0xffffffffu, pB, 2);
            if ((lane & 3) == 0) {
                y_s[bA][dloc] = pA;
                y_s[bB][dloc] = pB;
            }
        }
    }
    __syncthreads();

    // Combine + coalesced stores: out = y + dt*x*SBC + x
#pragma unroll
    for (int v = tid; v < 512; v += 256) {
        const int b = v >> 5, dq = (v & 31) << 2;
        const size_t g = (size_t)(b0 + b) * DD + d0 + dq;
        float4 xv = *(const float4*)&x[g];
        float4 dtv = *(const float4*)&dt_s[b][dq];
        float4 yv = *(const float4*)&y_s[b][dq];
        const float sbc = SBCs[b];
        float4 o;
        o.x = yv.x + fmaf(dtv.x * xv.x, sbc, xv.x);
        o.y = yv.y + fmaf(dtv.y * xv.y, sbc, xv.y);
        o.z = yv.z + fmaf(dtv.z * xv.z, sbc, xv.z);
        o.w = yv.w + fmaf(dtv.w * xv.w, sbc, xv.w);
        *(float4*)&out[g] = o;
    }
}

// ---------------------------------------------------------------------------
extern "C" void kernel_launch(void* const* d_in, const int* in_sizes, int n_in,
                              void* d_out, int out_size)
{
    const float* x    = (const float*)d_in[0];
    const float* h0   = (const float*)d_in[1];
    const float* Wx   = (const float*)d_in[2];
    const float* Wdt  = (const float*)d_in[3];
    const float* bdt  = (const float*)d_in[4];
    const float* Wbc  = (const float*)d_in[5];
    const float* Alog = (const float*)d_in[6];
    float* out = (float*)d_out;

    mamba_proj_kernel<<<dim3(2, 3, KSPLIT), 256>>>(x, Wx, Wbc);
    mamba_reduce_kernel<<<(BB * JJ) / 256, 256>>>();
    mamba_dt_kernel<<<dim3(DD / 128, BB / 32), 256>>>(Wdt, bdt);
    mamba_scan_kernel<<<dim3(DD / 128, BB / 16), 256>>>(x, h0, Alog, out);
}

// round 8
// speedup vs baseline: 1.0567x; 1.0567x over previous
#include <cuda_runtime.h>

#define BB 256
#define DD 5120
#define NN 16
#define RR 160
#define JJ 192          // RR + 32 (B/C projections)
#define KSPLIT 64
#define KCH (DD / KSPLIT)   // 80
#define BK 16

// Scratch (device globals — no allocations allowed)
__device__ float g_P[KSPLIT * BB * JJ];   // split-K partials (12.6 MB)
__device__ float g_T[BB * JJ];            // reduced projections
__device__ float g_DT[BB * DD];           // dt (5.2 MB)

__device__ __forceinline__ float ex2f(float v) {
    float r;
    asm("ex2.approx.ftz.f32 %0, %1;" : "=f"(r) : "f"(v));
    return r;
}

typedef unsigned long long ull;

__device__ __forceinline__ ull fma2(ull a, ull b, ull c) {
    ull d;
    asm("fma.rn.f32x2 %0, %1, %2, %3;" : "=l"(d) : "l"(a), "l"(b), "l"(c));
    return d;
}
__device__ __forceinline__ float2 unpk(ull v) {
    float2 r;
    asm("mov.b64 {%0, %1}, %2;" : "=f"(r.x), "=f"(r.y) : "l"(v));
    return r;
}

// ---------------------------------------------------------------------------
// Kernel 1: split-K GEMM. P[ks] = x[:, k-chunk] @ [W_x_dt | W_BC]
// PLUS: fire-and-forget L2 prefetch of h0 (84 MB across 384 blocks), so the
// scan kernel's h0 reads hit L2. DRAM is otherwise idle during the GEMM chain.
// Tile 128(M) x 64(N), BK=16, double-buffered, 256 threads, 8M x 4N micro.
// Grid (2, 3, 64) = 384 blocks.
// ---------------------------------------------------------------------------
__global__ __launch_bounds__(256) void mamba_proj_kernel(
    const float* __restrict__ x, const float* __restrict__ Wx,
    const float* __restrict__ Wbc, const float* __restrict__ h0)
{
    __shared__ float2 As2[2][BK][130];  // [buf][k][m] duplicated, padded
    __shared__ float  Bs[2][BK][64];    // [buf][k][n]
    const int m0 = blockIdx.x * 128;
    const int n0 = blockIdx.y * 64;
    const int k0 = blockIdx.z * KCH;
    const int tid = threadIdx.x;
    const int tx = tid & 15, ty = tid >> 4;   // micro coords: n=tx*4, m=ty*8

    // ---- h0 L2 prefetch: 655360 lines of 128B over 384 blocks ----
    {
        const int bid = blockIdx.x + blockIdx.y * 2 + blockIdx.z * 6;  // 0..383
        const size_t total = (size_t)BB * DD * NN;                     // floats
        size_t base = (size_t)bid * 1707 * 32;                         // floats
#pragma unroll
        for (int i = 0; i < 7; i++) {
            size_t off = base + ((size_t)(tid + i * 256)) * 32;
            if ((tid + i * 256) < 1707 && off < total)
                asm volatile("prefetch.global.L2 [%0];" :: "l"(h0 + off) : "memory");
        }
    }

    const int am = tid >> 2, akq = (tid & 3) << 2;   // A loader
    const int bk_ = tid >> 4, bn = (tid & 15) << 2;  // B loader

    // Branch-free W source (column j fixed per thread)
    const int j = n0 + bn;
    const float* bbase;
    size_t bstride;
    if (j < RR) { bbase = Wx + j;         bstride = RR; }
    else        { bbase = Wbc + (j - RR); bstride = 32; }

    const float* a0src = &x[(size_t)(m0 + am) * DD + k0 + akq];
    const float* a1src = a0src + (size_t)64 * DD;

    ull acc2[8][2] = {};

    // prologue: chunk 0
    float4 av0 = *(const float4*)a0src;
    float4 av1 = *(const float4*)a1src;
    float4 bv  = *(const float4*)&bbase[(size_t)(k0 + bk_) * bstride];
#pragma unroll
    for (int q = 0; q < 4; q++) {
        float a0 = ((const float*)&av0)[q], a1 = ((const float*)&av1)[q];
        As2[0][akq + q][am]      = make_float2(a0, a0);
        As2[0][akq + q][am + 64] = make_float2(a1, a1);
    }
    *(float4*)&Bs[0][bk_][bn] = bv;
    __syncthreads();

#pragma unroll
    for (int c = 0; c < KCH / BK; c++) {
        const int cur = c & 1;
        if (c + 1 < KCH / BK) {
            av0 = *(const float4*)(a0src + (c + 1) * BK);
            av1 = *(const float4*)(a1src + (c + 1) * BK);
            bv  = *(const float4*)&bbase[(size_t)(k0 + (c + 1) * BK + bk_) * bstride];
        }
#pragma unroll
        for (int kk = 0; kk < BK; kk++) {
            ulonglong2 bq = *(const ulonglong2*)&Bs[cur][kk][tx * 4];
            ulonglong2 aq0 = *(const ulonglong2*)&As2[cur][kk][ty * 8 + 0];
            ulonglong2 aq1 = *(const ulonglong2*)&As2[cur][kk][ty * 8 + 2];
            ulonglong2 aq2 = *(const ulonglong2*)&As2[cur][kk][ty * 8 + 4];
            ulonglong2 aq3 = *(const ulonglong2*)&As2[cur][kk][ty * 8 + 6];
            acc2[0][0] = fma2(aq0.x, bq.x, acc2[0][0]);
            acc2[0][1] = fma2(aq0.x, bq.y, acc2[0][1]);
            acc2[1][0] = fma2(aq0.y, bq.x, acc2[1][0]);
            acc2[1][1] = fma2(aq0.y, bq.y, acc2[1][1]);
            acc2[2][0] = fma2(aq1.x, bq.x, acc2[2][0]);
            acc2[2][1] = fma2(aq1.x, bq.y, acc2[2][1]);
            acc2[3][0] = fma2(aq1.y, bq.x, acc2[3][0]);
            acc2[3][1] = fma2(aq1.y, bq.y, acc2[3][1]);
            acc2[4][0] = fma2(aq2.x, bq.x, acc2[4][0]);
            acc2[4][1] = fma2(aq2.x, bq.y, acc2[4][1]);
            acc2[5][0] = fma2(aq2.y, bq.x, acc2[5][0]);
            acc2[5][1] = fma2(aq2.y, bq.y, acc2[5][1]);
            acc2[6][0] = fma2(aq3.x, bq.x, acc2[6][0]);
            acc2[6][1] = fma2(aq3.x, bq.y, acc2[6][1]);
            acc2[7][0] = fma2(aq3.y, bq.x, acc2[7][0]);
            acc2[7][1] = fma2(aq3.y, bq.y, acc2[7][1]);
        }
        if (c + 1 < KCH / BK) {
            const int nxt = cur ^ 1;
            __syncthreads();
#pragma unroll
            for (int q = 0; q < 4; q++) {
                float a0 = ((const float*)&av0)[q], a1 = ((const float*)&av1)[q];
                As2[nxt][akq + q][am]      = make_float2(a0, a0);
                As2[nxt][akq + q][am + 64] = make_float2(a1, a1);
            }
            *(float4*)&Bs[nxt][bk_][bn] = bv;
            __syncthreads();
        }
    }

    float* dst = &g_P[(size_t)blockIdx.z * (BB * JJ)];
#pragma unroll
    for (int i = 0; i < 8; i++) {
        float2 p0 = unpk(acc2[i][0]);
        float2 p1 = unpk(acc2[i][1]);
        *(float4*)&dst[(size_t)(m0 + ty * 8 + i) * JJ + n0 + tx * 4] =
            make_float4(p0.x, p0.y, p1.x, p1.y);
    }
}

// ---------------------------------------------------------------------------
// Kernel 1r: reduce split-K partials. One thread per float, grid 192.
// ---------------------------------------------------------------------------
__global__ __launch_bounds__(256) void mamba_reduce_kernel()
{
    const int idx = blockIdx.x * 256 + threadIdx.x;
    float s = 0.f;
#pragma unroll 16
    for (int ks = 0; ks < KSPLIT; ks++) s += g_P[ks * (BB * JJ) + idx];
    g_T[idx] = s;
}

// ---------------------------------------------------------------------------
// Kernel 2a: dt GEMM.  z = t @ W_dt + b_dt ; dt = softplus(z) -> g_DT
// Tile 32(b) x 128(d), 256 threads, thread owns 4b x 4 consecutive d.
// Ts stored PRE-DUPLICATED: broadcast LDS.64 is directly the FFMA2 operand.
// Grid (40, 8).
// ---------------------------------------------------------------------------
__global__ __launch_bounds__(256) void mamba_dt_kernel(
    const float* __restrict__ Wdt, const float* __restrict__ bdt)
{
    const int d0 = blockIdx.x * 128;
    const int b0 = blockIdx.y * 32;
    const int tid = threadIdx.x;
    const int tdx = tid & 31;     // d lane (4 consecutive d)
    const int tby = tid >> 5;     // warp id = b group (4 b per warp)

    __shared__ float2 Ts2[32][160];  // t tile, duplicated (41 KB)
    __shared__ float  Ws[16][128];   // W_dt chunk
    __shared__ float  bds[128];

    for (int v = tid; v < 1280; v += 256) {
        int b = v / 40, r4 = (v - b * 40) * 4;
        float4 t4 = *(const float4*)&g_T[(b0 + b) * JJ + r4];
        Ts2[b][r4 + 0] = make_float2(t4.x, t4.x);
        Ts2[b][r4 + 1] = make_float2(t4.y, t4.y);
        Ts2[b][r4 + 2] = make_float2(t4.z, t4.z);
        Ts2[b][r4 + 3] = make_float2(t4.w, t4.w);
    }
    if (tid < 128) bds[tid] = bdt[d0 + tid];

    ull acc2[4][2] = {};
    const int wr = tid >> 4;          // 0..15
    const int wc = (tid & 15) << 3;   // 0..120
    for (int rc = 0; rc < RR; rc += 16) {
        const float* wsrc = &Wdt[(size_t)(rc + wr) * DD + d0 + wc];
        float4 w0 = *(const float4*)wsrc;
        float4 w1 = *(const float4*)(wsrc + 4);
        __syncthreads();
        *(float4*)&Ws[wr][wc] = w0;
        *(float4*)&Ws[wr][wc + 4] = w1;
        __syncthreads();
#pragma unroll
        for (int rr = 0; rr < 16; rr++) {
            ulonglong2 wq = *(const ulonglong2*)&Ws[rr][tdx * 4];
            ull a0 = *(const ull*)&Ts2[tby * 4 + 0][rc + rr];  // bcast LDS.64
            ull a1 = *(const ull*)&Ts2[tby * 4 + 1][rc + rr];
            ull a2 = *(const ull*)&Ts2[tby * 4 + 2][rc + rr];
            ull a3 = *(const ull*)&Ts2[tby * 4 + 3][rc + rr];
            acc2[0][0] = fma2(a0, wq.x, acc2[0][0]);
            acc2[0][1] = fma2(a0, wq.y, acc2[0][1]);
            acc2[1][0] = fma2(a1, wq.x, acc2[1][0]);
            acc2[1][1] = fma2(a1, wq.y, acc2[1][1]);
            acc2[2][0] = fma2(a2, wq.x, acc2[2][0]);
            acc2[2][1] = fma2(a2, wq.y, acc2[2][1]);
            acc2[3][0] = fma2(a3, wq.x, acc2[3][0]);
            acc2[3][1] = fma2(a3, wq.y, acc2[3][1]);
        }
    }

    float4 bdv = *(const float4*)&bds[tdx * 4];
#pragma unroll
    for (int bi = 0; bi < 4; bi++) {
        const int bl = tby * 4 + bi;
        float2 p0 = unpk(acc2[bi][0]);
        float2 p1 = unpk(acc2[bi][1]);
        float z0 = p0.x + bdv.x, z1 = p0.y + bdv.y;
        float z2 = p1.x + bdv.z, z3 = p1.y + bdv.w;
        float4 dtv;
        dtv.x = fmaxf(z0, 0.f) + log1pf(__expf(-fabsf(z0)));
        dtv.y = fmaxf(z1, 0.f) + log1pf(__expf(-fabsf(z1)));
        dtv.z = fmaxf(z2, 0.f) + log1pf(__expf(-fabsf(z2)));
        dtv.w = fmaxf(z3, 0.f) + log1pf(__expf(-fabsf(z3)));
        *(float4*)&g_DT[(size_t)(b0 + bl) * DD + d0 + tdx * 4] = dtv;
    }
}

// ---------------------------------------------------------------------------
// Kernel 2b: h0 stream (h0 now mostly L2-resident from the proj prefetch).
//   y[b,d] = sum_n ex2(A2[d,n]*dt)*h0[b,d,n]*C[b,n] + dt*x*SBC[b] + x
// Dual-stream depth-2 prefetch. Block (128 d, 16 b). Grid (40, 16) = 640.
// ---------------------------------------------------------------------------
__global__ __launch_bounds__(256) void mamba_scan_kernel(
    const float* __restrict__ x, const float* __restrict__ h0,
    const float* __restrict__ Alog, float* __restrict__ out)
{
    const int d0 = blockIdx.x * 128;
    const int b0 = blockIdx.y * 16;
    const int tid = threadIdx.x;
    const int lane = tid & 31;
    const int w = tid >> 5;

    __shared__ float A2s[128][16];   // -exp(A_log)*log2(e)
    __shared__ float dt_s[16][128];
    __shared__ float y_s[16][128];
    __shared__ float Cs[16][16];
    __shared__ float SBCs[16];

    // A2s (vectorized exp)
#pragma unroll
    for (int v = tid; v < 512; v += 256) {
        int di = v >> 2, n4 = (v & 3) << 2;
        float4 al = *(const float4*)&Alog[(size_t)(d0 + di) * NN + n4];
        float4 o;
        o.x = -__expf(al.x) * 1.44269504f;
        o.y = -__expf(al.y) * 1.44269504f;
        o.z = -__expf(al.z) * 1.44269504f;
        o.w = -__expf(al.w) * 1.44269504f;
        *(float4*)&A2s[di][n4] = o;
    }
    // dt tile
#pragma unroll
    for (int v = tid; v < 512; v += 256) {
        int b = v >> 5, dq = (v & 31) << 2;
        *(float4*)&dt_s[b][dq] =
            *(const float4*)&g_DT[(size_t)(b0 + b) * DD + d0 + dq];
    }
    // C, SBC
    {
        int b = tid >> 4, n = tid & 15;
        Cs[b][n] = g_T[(b0 + b) * JJ + RR + NN + n];
    }
    if (tid < 16) {
        float s = 0.f;
#pragma unroll
        for (int n = 0; n < NN; n++)
            s += g_T[(b0 + tid) * JJ + RR + n] * g_T[(b0 + tid) * JJ + RR + NN + n];
        SBCs[tid] = s;
    }
    __syncthreads();

    // Dual-stream coalesced h0 sweep. Lane l -> (d = dg*8 + l/4, n=(l&3)*4..+3).
    {
        const int l4 = lane >> 2;
        const int n4 = (lane & 3) << 2;
        const int bA = w * 2, bB = w * 2 + 1;

        const float* hpA = &h0[((size_t)(b0 + bA) * DD + d0 + l4) * NN + n4];
        const float* hpB = hpA + (size_t)DD * NN;

        const float4 cA = *(const float4*)&Cs[bA][n4];   // hoisted
        const float4 cB = *(const float4*)&Cs[bB][n4];

        float4 hA0 = __ldcs((const float4*)hpA);
        float4 hB0 = __ldcs((const float4*)hpB);
        float4 hA1 = __ldcs((const float4*)(hpA + 128));
        float4 hB1 = __ldcs((const float4*)(hpB + 128));

#pragma unroll
        for (int dg = 0; dg < 16; dg++) {
            const int dloc = dg * 8 + l4;
            const float4 a2 = *(const float4*)&A2s[dloc][n4];
            const float dtA = dt_s[bA][dloc];
            const float dtB = dt_s[bB][dloc];

            float pA = ex2f(a2.x * dtA) * hA0.x * cA.x;
            pA = fmaf(ex2f(a2.y * dtA) * hA0.y, cA.y, pA);
            pA = fmaf(ex2f(a2.z * dtA) * hA0.z, cA.z, pA);
            pA = fmaf(ex2f(a2.w * dtA) * hA0.w, cA.w, pA);

            float pB = ex2f(a2.x * dtB) * hB0.x * cB.x;
            pB = fmaf(ex2f(a2.y * dtB) * hB0.y, cB.y, pB);
            pB = fmaf(ex2f(a2.z * dtB) * hB0.z, cB.z, pB);
            pB = fmaf(ex2f(a2.w * dtB) * hB0.w, cB.w, pB);

            hA0 = hA1; hB0 = hB1;
            if (dg < 14) {
                hA1 = __ldcs((const float4*)(hpA + (size_t)(dg + 2) * 128));
                hB1 = __ldcs((const float4*)(hpB + (size_t)(dg + 2) * 128));
            }

            pA += __shfl_xor_sync(0xffffffffu, pA, 1);
            pA += __shfl_xor_sync(0xffffffffu, pA, 2);
            pB += __shfl_xor_sync(0xffffffffu, pB, 1);
            pB += __shfl_xor_sync(0xffffffffu, pB, 2);
            if ((lane & 3) == 0) {
                y_s[bA][dloc] = pA;
                y_s[bB][dloc] = pB;
            }
        }
    }
    __syncthreads();

    // Combine + coalesced stores: out = y + dt*x*SBC + x
#pragma unroll
    for (int v = tid; v < 512; v += 256) {
        const int b = v >> 5, dq = (v & 31) << 2;
        const size_t g = (size_t)(b0 + b) * DD + d0 + dq;
        float4 xv = *(const float4*)&x[g];
        float4 dtv = *(const float4*)&dt_s[b][dq];
        float4 yv = *(const float4*)&y_s[b][dq];
        const float sbc = SBCs[b];
        float4 o;
        o.x = yv.x + fmaf(dtv.x * xv.x, sbc, xv.x);
        o.y = yv.y + fmaf(dtv.y * xv.y, sbc, xv.y);
        o.z = yv.z + fmaf(dtv.z * xv.z, sbc, xv.z);
        o.w = yv.w + fmaf(dtv.w * xv.w, sbc, xv.w);
        *(float4*)&out[g] = o;
    }
}

// ---------------------------------------------------------------------------
extern "C" void kernel_launch(void* const* d_in, const int* in_sizes, int n_in,
                              void* d_out, int out_size)
{
    const float* x    = (const float*)d_in[0];
    const float* h0   = (const float*)d_in[1];
    const float* Wx   = (const float*)d_in[2];
    const float* Wdt  = (const float*)d_in[3];
    const float* bdt  = (const float*)d_in[4];
    const float* Wbc  = (const float*)d_in[5];
    const float* Alog = (const float*)d_in[6];
    float* out = (float*)d_out;

    mamba_proj_kernel<<<dim3(2, 3, KSPLIT), 256>>>(x, Wx, Wbc, h0);
    mamba_reduce_kernel<<<(BB * JJ) / 256, 256>>>();
    mamba_dt_kernel<<<dim3(DD / 128, BB / 32), 256>>>(Wdt, bdt);
    mamba_scan_kernel<<<dim3(DD / 128, BB / 16), 256>>>(x, h0, Alog, out);
}